// round 16
// baseline (speedup 1.0000x reference)
#include <cuda_runtime.h>
#include <cuda_fp16.h>
#include <math.h>
#include <stdint.h>

#define BB 8
#define TT 2048
#define CC 384
#define HH 6
#define HS 64
#define BT (BB*TT)     /* 16384 */
#define FF 1536
#define NQKV 1152
/* 384^-0.5 * log2(e): softmax computed as exp2 */
#define QSCALE 0.07362223f

// ---------------- scratch ----------------
__device__ __align__(256) __half g_h [BT*CC];
__device__ __align__(256) __half g_q [BT*CC];
__device__ __align__(256) __half g_k [BT*CC];
__device__ __align__(256) __half g_v [BT*CC];
__device__ __align__(256) __half g_att[BT*CC];
__device__ __align__(256) float  g_x1[BT*CC];
__device__ __align__(256) __half g_h2[BT*CC];
__device__ __align__(256) __half g_ff[BT*FF];
__device__ __align__(256) __half g_wqkv[CC*NQKV];
__device__ __align__(256) __half g_wo[CC*CC];
__device__ __align__(256) __half g_w1[CC*FF];
__device__ __align__(256) __half g_w2[FF*CC];

// ---------------- asm helpers ----------------
__device__ __forceinline__ uint32_t smem_u32(const void* p) {
    return (uint32_t)__cvta_generic_to_shared(p);
}
__device__ __forceinline__ void cp16(uint32_t s, const void* g) {
    asm volatile("cp.async.cg.shared.global [%0],[%1],16;" :: "r"(s), "l"(g));
}
__device__ __forceinline__ void cp_commit() { asm volatile("cp.async.commit_group;"); }
template<int N> __device__ __forceinline__ void cp_wait() {
    asm volatile("cp.async.wait_group %0;" :: "n"(N));
}
__device__ __forceinline__ void ldm_x4(uint32_t& r0, uint32_t& r1, uint32_t& r2, uint32_t& r3, uint32_t a) {
    asm volatile("ldmatrix.sync.aligned.m8n8.x4.shared.b16 {%0,%1,%2,%3},[%4];"
                 : "=r"(r0), "=r"(r1), "=r"(r2), "=r"(r3) : "r"(a));
}
__device__ __forceinline__ void ldm_x4t(uint32_t& r0, uint32_t& r1, uint32_t& r2, uint32_t& r3, uint32_t a) {
    asm volatile("ldmatrix.sync.aligned.m8n8.x4.trans.shared.b16 {%0,%1,%2,%3},[%4];"
                 : "=r"(r0), "=r"(r1), "=r"(r2), "=r"(r3) : "r"(a));
}
__device__ __forceinline__ void mma16(float4& d,
                                      uint32_t a0, uint32_t a1, uint32_t a2, uint32_t a3,
                                      uint32_t b0, uint32_t b1) {
    asm("mma.sync.aligned.m16n8k16.row.col.f32.f16.f16.f32 "
        "{%0,%1,%2,%3},{%4,%5,%6,%7},{%8,%9},{%0,%1,%2,%3};"
        : "+f"(d.x), "+f"(d.y), "+f"(d.z), "+f"(d.w)
        : "r"(a0), "r"(a1), "r"(a2), "r"(a3), "r"(b0), "r"(b1));
}
__device__ __forceinline__ float tanh_fast(float x) {
    float y; asm("tanh.approx.f32 %0,%1;" : "=f"(y) : "f"(x)); return y;
}
__device__ __forceinline__ uint32_t h2u(float a, float b) {
    __half2 h = __floats2half2_rn(a, b);
    return *(uint32_t*)&h;
}
__device__ __forceinline__ uint32_t hex2u(uint32_t x) {
    uint32_t y; asm("ex2.approx.f16x2 %0,%1;" : "=r"(y) : "r"(x)); return y;
}
__device__ __forceinline__ uint32_t hadd2u(uint32_t a, uint32_t b) {
    uint32_t c; asm("add.f16x2 %0,%1,%2;" : "=r"(c) : "r"(a), "r"(b)); return c;
}

// ---------------- weight convert + QKV repack ----------------
__global__ __launch_bounds__(256) void w_pack(const float* __restrict__ Wq,
                                              const float* __restrict__ Wk,
                                              const float* __restrict__ Wv,
                                              const float* __restrict__ Wo,
                                              const float* __restrict__ W1,
                                              const float* __restrict__ W2,
                                              __half* __restrict__ wqkv,
                                              __half* __restrict__ wo,
                                              __half* __restrict__ w1,
                                              __half* __restrict__ w2) {
    int t0 = blockIdx.x * 256 + threadIdx.x;
    int stride = gridDim.x * 256;
    const int NQ4 = 3 * HH * CC * HS / 4;
    for (int i = t0; i < NQ4; i += stride) {
        int d  = (i & 15) << 2;
        int c  = (i >> 4) % CC;
        int hz = i / (16 * CC);
        int z = hz / HH, hh = hz - z * HH;
        const float* W = (z == 0) ? Wq : (z == 1) ? Wk : Wv;
        float4 v = *(const float4*)&W[((size_t)hh * CC + c) * HS + d];
        __half* dst = &wqkv[(size_t)c * NQKV + z * CC + hh * HS + d];
        *(__half2*)dst       = __floats2half2_rn(v.x, v.y);
        *(__half2*)(dst + 2) = __floats2half2_rn(v.z, v.w);
    }
    for (int i = t0; i < CC * CC / 4; i += stride) {
        float4 v = *(const float4*)&Wo[i * 4];
        *(__half2*)&wo[i * 4]     = __floats2half2_rn(v.x, v.y);
        *(__half2*)&wo[i * 4 + 2] = __floats2half2_rn(v.z, v.w);
    }
    for (int i = t0; i < CC * FF / 4; i += stride) {
        float4 v = *(const float4*)&W1[i * 4];
        *(__half2*)&w1[i * 4]     = __floats2half2_rn(v.x, v.y);
        *(__half2*)&w1[i * 4 + 2] = __floats2half2_rn(v.z, v.w);
    }
    for (int i = t0; i < FF * CC / 4; i += stride) {
        float4 v = *(const float4*)&W2[i * 4];
        *(__half2*)&w2[i * 4]     = __floats2half2_rn(v.x, v.y);
        *(__half2*)&w2[i * 4 + 2] = __floats2half2_rn(v.z, v.w);
    }
}

// ---------------- LayerNorm -> half ----------------
__global__ __launch_bounds__(128) void ln_half(const float* __restrict__ x,
                                               const float* __restrict__ w,
                                               __half* __restrict__ out) {
    int row = blockIdx.x;
    const float* xr = x + (size_t)row * CC;
    int tid = threadIdx.x;
    float v0 = xr[tid], v1 = xr[tid + 128], v2 = xr[tid + 256];
    float s = v0 + v1 + v2;
    __shared__ float red[4], red2[4];
    #pragma unroll
    for (int o = 16; o > 0; o >>= 1) s += __shfl_xor_sync(0xffffffffu, s, o);
    if ((tid & 31) == 0) red[tid >> 5] = s;
    __syncthreads();
    float mean = (red[0] + red[1] + red[2] + red[3]) * (1.0f / CC);
    float d0 = v0 - mean, d1 = v1 - mean, d2 = v2 - mean;
    float q = d0*d0 + d1*d1 + d2*d2;
    #pragma unroll
    for (int o = 16; o > 0; o >>= 1) q += __shfl_xor_sync(0xffffffffu, q, o);
    if ((tid & 31) == 0) red2[tid >> 5] = q;
    __syncthreads();
    float var = (red2[0] + red2[1] + red2[2] + red2[3]) * (1.0f / CC);
    float rstd = rsqrtf(var + 1e-5f);
    __half* orow = out + (size_t)row * CC;
    orow[tid]       = __float2half(d0 * rstd * w[tid]);
    orow[tid + 128] = __float2half(d1 * rstd * w[tid + 128]);
    orow[tid + 256] = __float2half(d2 * rstd * w[tid + 256]);
}

#define AST 40
#define BST 136

// ---------------- epilogue (shared by both GEMM variants) ----------------
template<int MODE>
__device__ __forceinline__ void epi_store(int r, int col, float o0, float o1, int N,
                                          void* Cout, const float* res, const float* bias,
                                          __half* qo, __half* ko, __half* vo) {
    const float cg = 0.7978845608028654f;
    if (MODE == 0) {
        int z = col / CC; int rem = col - z * CC;
        int hh = rem >> 6, d = rem & 63;
        __half* Oz = (z == 0) ? qo : (z == 1) ? ko : vo;
        float sc = (z == 0) ? QSCALE : 1.0f;
        int bb = r >> 11, t = r & (TT - 1);
        *(__half2*)&Oz[((size_t)(bb * HH + hh) * TT + t) * HS + d] =
            __floats2half2_rn(o0 * sc, o1 * sc);
    } else if (MODE == 1) {
        float2 rr = *(const float2*)&res[(size_t)r * N + col];
        float2 bb = *(const float2*)&bias[col];
        *(float2*)((float*)Cout + (size_t)r * N + col) =
            make_float2(o0 + rr.x + bb.x, o1 + rr.y + bb.y);
    } else if (MODE == 2) {
        o0 = 0.5f * o0 * (1.0f + tanh_fast(cg * (o0 + 0.044715f * o0 * o0 * o0)));
        o1 = 0.5f * o1 * (1.0f + tanh_fast(cg * (o1 + 0.044715f * o1 * o1 * o1)));
        *(__half2*)((__half*)Cout + (size_t)r * N + col) = __floats2half2_rn(o0, o1);
    } else {
        float2 rr = *(const float2*)&res[(size_t)r * N + col];
        *(float2*)((float*)Cout + (size_t)r * N + col) =
            make_float2(o0 + rr.x, o1 + rr.y);
    }
}

// ---------------- fp16 GEMM A: 128x128x32, 256 thr, 2 CTAs/SM ----------------
#define SM_GEMM ((3*128*AST + 3*32*BST) * 2)
template<int MODE>
__global__ __launch_bounds__(256, 2) void hgemm(const __half* __restrict__ A,
                                                const __half* __restrict__ B,
                                                void* __restrict__ Cout,
                                                const float* __restrict__ res,
                                                const float* __restrict__ bias,
                                                __half* __restrict__ qo,
                                                __half* __restrict__ ko,
                                                __half* __restrict__ vo,
                                                int M, int N, int K) {
    extern __shared__ __half smg[];
    __half* Asm = smg;
    __half* Bsm = smg + 3 * 128 * AST;
    int bm = blockIdx.x * 128, bn = blockIdx.y * 128;
    int tid = threadIdx.x;
    int wid = tid >> 5, lane = tid & 31, g = lane >> 2, tg = lane & 3;
    int wm = wid >> 2, wn = wid & 3;
    int l4 = lane & 15, lh = lane >> 4;
    float4 acc[4][4];
    #pragma unroll
    for (int i = 0; i < 4; i++)
        #pragma unroll
        for (int j = 0; j < 4; j++) acc[i][j] = make_float4(0.f, 0.f, 0.f, 0.f);

    int KT = K >> 5;
    int ar0 = tid >> 2, ac0 = tid & 3;
    int ar1 = (tid + 256) >> 2;
    int brr = tid >> 4, bcc = tid & 15;
    auto load_tile = [&](int kt, int st) {
        __half* As = Asm + st * 128 * AST;
        __half* Bs = Bsm + st * 32 * BST;
        const __half* Ag = A + (size_t)bm * K + kt * 32;
        const __half* Bg = B + (size_t)(kt * 32) * N + bn;
        cp16(smem_u32(&As[ar0 * AST + ac0 * 8]), Ag + (size_t)ar0 * K + ac0 * 8);
        cp16(smem_u32(&As[ar1 * AST + ac0 * 8]), Ag + (size_t)ar1 * K + ac0 * 8);
        cp16(smem_u32(&Bs[brr * BST + bcc * 8]), Bg + (size_t)brr * N + bcc * 8);
        cp16(smem_u32(&Bs[(brr + 16) * BST + bcc * 8]), Bg + (size_t)(brr + 16) * N + bcc * 8);
        cp_commit();
    };
    load_tile(0, 0);
    if (KT > 1) load_tile(1, 1);

    for (int kt = 0; kt < KT; kt++) {
        int st = kt % 3;
        if (kt + 1 < KT) cp_wait<1>(); else cp_wait<0>();
        __syncthreads();
        __half* As = Asm + st * 128 * AST;
        __half* Bs = Bsm + st * 32 * BST;
        if (kt + 2 < KT) load_tile(kt + 2, (kt + 2) % 3);
        #pragma unroll
        for (int ks = 0; ks < 2; ks++) {
            uint32_t aF[4][4];
            #pragma unroll
            for (int mt = 0; mt < 4; mt++) {
                int row = wm * 64 + mt * 16 + l4;
                ldm_x4(aF[mt][0], aF[mt][1], aF[mt][2], aF[mt][3],
                       smem_u32(&As[row * AST + ks * 16 + lh * 8]));
            }
            #pragma unroll
            for (int ntp = 0; ntp < 2; ntp++) {
                uint32_t b00, b01, b10, b11;
                int n0 = wn * 32 + ntp * 16;
                ldm_x4t(b00, b01, b10, b11,
                        smem_u32(&Bs[(ks * 16 + l4) * BST + n0 + lh * 8]));
                #pragma unroll
                for (int mt = 0; mt < 4; mt++) {
                    mma16(acc[mt][ntp * 2],     aF[mt][0], aF[mt][1], aF[mt][2], aF[mt][3], b00, b01);
                    mma16(acc[mt][ntp * 2 + 1], aF[mt][0], aF[mt][1], aF[mt][2], aF[mt][3], b10, b11);
                }
            }
        }
    }
    #pragma unroll
    for (int mt = 0; mt < 4; mt++)
        #pragma unroll
        for (int nt = 0; nt < 4; nt++) {
            int r0 = bm + wm * 64 + mt * 16 + g;
            int col = bn + wn * 32 + nt * 8 + tg * 2;
            float vv[4] = {acc[mt][nt].x, acc[mt][nt].y, acc[mt][nt].z, acc[mt][nt].w};
            #pragma unroll
            for (int hf = 0; hf < 2; hf++)
                epi_store<MODE>(r0 + hf * 8, col, vv[hf * 2], vv[hf * 2 + 1],
                                N, Cout, res, bias, qo, ko, vo);
        }
}

// ---------------- fp16 GEMM B: 64x128x32, 128 thr, 4 CTAs/SM ----------------
#define SM_GEMM64 ((3*64*AST + 3*32*BST) * 2)
template<int MODE>
__global__ __launch_bounds__(128, 4) void hgemm64(const __half* __restrict__ A,
                                                  const __half* __restrict__ B,
                                                  void* __restrict__ Cout,
                                                  const float* __restrict__ res,
                                                  const float* __restrict__ bias,
                                                  __half* __restrict__ qo,
                                                  __half* __restrict__ ko,
                                                  __half* __restrict__ vo,
                                                  int M, int N, int K) {
    extern __shared__ __half smg[];
    __half* Asm = smg;
    __half* Bsm = smg + 3 * 64 * AST;
    int bm = blockIdx.x * 64, bn = blockIdx.y * 128;
    int tid = threadIdx.x;
    int wid = tid >> 5, lane = tid & 31, g = lane >> 2, tg = lane & 3;
    int wm = wid >> 1, wn = wid & 1;
    int l4 = lane & 15, lh = lane >> 4;
    float4 acc[2][8];
    #pragma unroll
    for (int i = 0; i < 2; i++)
        #pragma unroll
        for (int j = 0; j < 8; j++) acc[i][j] = make_float4(0.f, 0.f, 0.f, 0.f);

    int KT = K >> 5;
    int ar0 = tid >> 2, ac0 = tid & 3;
    int ar1 = (tid + 128) >> 2;
    int brr = tid >> 4, bcc = tid & 15;
    auto load_tile = [&](int kt, int st) {
        __half* As = Asm + st * 64 * AST;
        __half* Bs = Bsm + st * 32 * BST;
        const __half* Ag = A + (size_t)bm * K + kt * 32;
        const __half* Bg = B + (size_t)(kt * 32) * N + bn;
        cp16(smem_u32(&As[ar0 * AST + ac0 * 8]), Ag + (size_t)ar0 * K + ac0 * 8);
        cp16(smem_u32(&As[ar1 * AST + ac0 * 8]), Ag + (size_t)ar1 * K + ac0 * 8);
        #pragma unroll
        for (int j = 0; j < 4; j++)
            cp16(smem_u32(&Bs[(brr + j * 8) * BST + bcc * 8]),
                 Bg + (size_t)(brr + j * 8) * N + bcc * 8);
        cp_commit();
    };
    load_tile(0, 0);
    if (KT > 1) load_tile(1, 1);

    for (int kt = 0; kt < KT; kt++) {
        int st = kt % 3;
        if (kt + 1 < KT) cp_wait<1>(); else cp_wait<0>();
        __syncthreads();
        __half* As = Asm + st * 64 * AST;
        __half* Bs = Bsm + st * 32 * BST;
        if (kt + 2 < KT) load_tile(kt + 2, (kt + 2) % 3);
        #pragma unroll
        for (int ks = 0; ks < 2; ks++) {
            uint32_t aF[2][4];
            #pragma unroll
            for (int mt = 0; mt < 2; mt++) {
                int row = wm * 32 + mt * 16 + l4;
                ldm_x4(aF[mt][0], aF[mt][1], aF[mt][2], aF[mt][3],
                       smem_u32(&As[row * AST + ks * 16 + lh * 8]));
            }
            #pragma unroll
            for (int ntp = 0; ntp < 4; ntp++) {
                uint32_t b00, b01, b10, b11;
                int n0 = wn * 64 + ntp * 16;
                ldm_x4t(b00, b01, b10, b11,
                        smem_u32(&Bs[(ks * 16 + l4) * BST + n0 + lh * 8]));
                #pragma unroll
                for (int mt = 0; mt < 2; mt++) {
                    mma16(acc[mt][ntp * 2],     aF[mt][0], aF[mt][1], aF[mt][2], aF[mt][3], b00, b01);
                    mma16(acc[mt][ntp * 2 + 1], aF[mt][0], aF[mt][1], aF[mt][2], aF[mt][3], b10, b11);
                }
            }
        }
    }
    #pragma unroll
    for (int mt = 0; mt < 2; mt++)
        #pragma unroll
        for (int nt = 0; nt < 8; nt++) {
            int r0 = bm + wm * 32 + mt * 16 + g;
            int col = bn + wn * 64 + nt * 8 + tg * 2;
            float vv[4] = {acc[mt][nt].x, acc[mt][nt].y, acc[mt][nt].z, acc[mt][nt].w};
            #pragma unroll
            for (int hf = 0; hf < 2; hf++)
                epi_store<MODE>(r0 + hf * 8, col, vv[hf * 2], vv[hf * 2 + 1],
                                N, Cout, res, bias, qo, ko, vo);
        }
}

// ---------------- fp16 flash attention: 128 thr, 4 warps x 32 q-rows, 3 CTAs/SM ----------------
// 2 m-tiles/warp: K/V fragments reused -> MMA:LDSM = 4:1. Bq=128, Bk=64, 2-stage.
#define SM_ATTN ((128*64 + 2*64*64 + 2*64*64) * 2)   /* 48 KB */
__global__ __launch_bounds__(128, 3) void attn_h(const __half* __restrict__ Q,
                                                 const __half* __restrict__ K,
                                                 const __half* __restrict__ V,
                                                 __half* __restrict__ Og) {
    extern __shared__ __half sm[];
    __half* Qs = sm;                 // [128][64] swizzled
    __half* Ks = Qs + 128 * 64;      // [2][64][64] swizzled
    __half* Vs = Ks + 2 * 64 * 64;   // [2][64][64] swizzled

    int q0 = blockIdx.x * 128;
    int h = blockIdx.y, b = blockIdx.z;
    size_t base = (size_t)(b * HH + h) * TT * HS;
    int tid = threadIdx.x;
    int wid = tid >> 5, lane = tid & 31, g = lane >> 2, tg = lane & 3;
    int l4 = lane & 15, lh = lane >> 4;

    const __half* Qp = Q + base + (size_t)q0 * HS;
    #pragma unroll
    for (int i = 0; i < 8; i++) {
        int idx = tid + i * 128;
        int r = idx >> 3, c = idx & 7;
        cp16(smem_u32(&Qs[r * 64 + ((c ^ (r & 7)) << 3)]), Qp + (size_t)r * HS + c * 8);
    }
    auto load_kv = [&](int it, int buf) {
        const __half* Kp = K + base + (size_t)(it * 64) * HS;
        const __half* Vp = V + base + (size_t)(it * 64) * HS;
        #pragma unroll
        for (int i = 0; i < 4; i++) {
            int idx = tid + i * 128;
            int r = idx >> 3, c = idx & 7;
            int sp = buf * 4096 + r * 64 + ((c ^ (r & 7)) << 3);
            cp16(smem_u32(&Ks[sp]), Kp + (size_t)r * HS + c * 8);
            cp16(smem_u32(&Vs[sp]), Vp + (size_t)r * HS + c * 8);
        }
    };
    load_kv(0, 0);
    cp_commit();
    load_kv(1, 1);
    cp_commit();
    cp_wait<1>();
    __syncthreads();

    // Q fragments: 2 m-tiles of 16 rows per warp
    uint32_t qF[2][4][4];
    #pragma unroll
    for (int mt = 0; mt < 2; mt++) {
        int qrow = (wid << 5) + (mt << 4) + l4;
        #pragma unroll
        for (int dk = 0; dk < 4; dk++) {
            int ch = dk * 2 + lh;
            ldm_x4(qF[mt][dk][0], qF[mt][dk][1], qF[mt][dk][2], qF[mt][dk][3],
                   smem_u32(&Qs[qrow * 64 + ((ch ^ (qrow & 7)) << 3)]));
        }
    }

    int krow_base = (lane & 7) + ((lane & 16) >> 1);
    int kch_half = (lane >> 3) & 1;
    uint32_t Kb0 = smem_u32(Ks), Vb0 = smem_u32(Vs);
    uint32_t koff[4], voff[4];
    #pragma unroll
    for (int dk = 0; dk < 4; dk++) {
        int ch = dk * 2 + kch_half;
        koff[dk] = (uint32_t)(krow_base * 128 + (((ch ^ (krow_base & 7)) << 4)));
    }
    #pragma unroll
    for (int np = 0; np < 4; np++) {
        int ch = np * 2 + lh;
        voff[np] = (uint32_t)(l4 * 128 + (((ch ^ (l4 & 7)) << 4)));
    }

    float4 Oacc[2][8];
    #pragma unroll
    for (int mt = 0; mt < 2; mt++)
        #pragma unroll
        for (int j = 0; j < 8; j++) Oacc[mt][j] = make_float4(0.f, 0.f, 0.f, 0.f);
    float ls0[2] = {0.f, 0.f}, ls1[2] = {0.f, 0.f};

    const int NT = TT / 64;
    for (int it = 0; it < NT; it++) {
        int buf = it & 1;
        uint32_t kb = Kb0 + buf * 8192;
        uint32_t vb = Vb0 + buf * 8192;
        uint32_t hacc0[2] = {0u, 0u}, hacc1[2] = {0u, 0u};
        #pragma unroll
        for (int ntp = 0; ntp < 4; ntp++) {
            uint32_t kbase = kb + ntp * 2048;
            uint32_t vbase = vb + ntp * 2048;
            float4 s0[2], s1[2];
            #pragma unroll
            for (int mt = 0; mt < 2; mt++) {
                s0[mt] = make_float4(0.f, 0.f, 0.f, 0.f);
                s1[mt] = make_float4(0.f, 0.f, 0.f, 0.f);
            }
            #pragma unroll
            for (int dk = 0; dk < 4; dk++) {
                uint32_t k0, k1, k2, k3;
                ldm_x4(k0, k1, k2, k3, kbase + koff[dk]);
                #pragma unroll
                for (int mt = 0; mt < 2; mt++) {
                    mma16(s0[mt], qF[mt][dk][0], qF[mt][dk][1], qF[mt][dk][2], qF[mt][dk][3], k0, k1);
                    mma16(s1[mt], qF[mt][dk][0], qF[mt][dk][1], qF[mt][dk][2], qF[mt][dk][3], k2, k3);
                }
            }
            uint32_t p[2][4];
            #pragma unroll
            for (int mt = 0; mt < 2; mt++) {
                p[mt][0] = hex2u(h2u(s0[mt].x, s0[mt].y));
                p[mt][1] = hex2u(h2u(s0[mt].z, s0[mt].w));
                p[mt][2] = hex2u(h2u(s1[mt].x, s1[mt].y));
                p[mt][3] = hex2u(h2u(s1[mt].z, s1[mt].w));
                hacc0[mt] = hadd2u(hacc0[mt], hadd2u(p[mt][0], p[mt][2]));
                hacc1[mt] = hadd2u(hacc1[mt], hadd2u(p[mt][1], p[mt][3]));
            }
            #pragma unroll
            for (int np = 0; np < 4; np++) {
                uint32_t v0, v1, v2, v3;
                ldm_x4t(v0, v1, v2, v3, vbase + voff[np]);
                #pragma unroll
                for (int mt = 0; mt < 2; mt++) {
                    mma16(Oacc[mt][np * 2],     p[mt][0], p[mt][1], p[mt][2], p[mt][3], v0, v1);
                    mma16(Oacc[mt][np * 2 + 1], p[mt][0], p[mt][1], p[mt][2], p[mt][3], v2, v3);
                }
            }
        }
        #pragma unroll
        for (int mt = 0; mt < 2; mt++) {
            float2 f0 = __half22float2(*(__half2*)&hacc0[mt]);
            float2 f1 = __half22float2(*(__half2*)&hacc1[mt]);
            ls0[mt] += f0.x + f0.y;
            ls1[mt] += f1.x + f1.y;
        }
        __syncthreads();
        if (it + 2 < NT) { load_kv(it + 2, buf); cp_commit(); }
        if (it + 1 < NT) {
            if (it + 2 < NT) cp_wait<1>(); else cp_wait<0>();
            __syncthreads();
        }
    }
    #pragma unroll
    for (int mt = 0; mt < 2; mt++) {
        ls0[mt] += __shfl_xor_sync(0xffffffffu, ls0[mt], 1);
        ls0[mt] += __shfl_xor_sync(0xffffffffu, ls0[mt], 2);
        ls1[mt] += __shfl_xor_sync(0xffffffffu, ls1[mt], 1);
        ls1[mt] += __shfl_xor_sync(0xffffffffu, ls1[mt], 2);
        float i0 = 1.0f / ls0[mt], i1 = 1.0f / ls1[mt];
        int r0 = q0 + (wid << 5) + (mt << 4) + g;
        #pragma unroll
        for (int nt = 0; nt < 8; nt++) {
            int col = h * HS + nt * 8 + tg * 2;
            *(__half2*)&Og[(size_t)(b * TT + r0) * CC + col] =
                __floats2half2_rn(Oacc[mt][nt].x * i0, Oacc[mt][nt].y * i0);
            *(__half2*)&Og[(size_t)(b * TT + r0 + 8) * CC + col] =
                __floats2half2_rn(Oacc[mt][nt].z * i1, Oacc[mt][nt].w * i1);
        }
    }
}

// ---------------- launch ----------------
extern "C" void kernel_launch(void* const* d_in, const int* in_sizes, int n_in,
                              void* d_out, int out_size) {
    (void)in_sizes; (void)n_in; (void)out_size;
    const float* x     = (const float*)d_in[0];
    const float* ln1_w = (const float*)d_in[1];
    const float* ln2_w = (const float*)d_in[2];
    const float* Wq    = (const float*)d_in[3];
    const float* Wk    = (const float*)d_in[4];
    const float* Wv    = (const float*)d_in[5];
    const float* Wo    = (const float*)d_in[6];
    const float* bo    = (const float*)d_in[7];
    const float* W1    = (const float*)d_in[8];
    const float* W2    = (const float*)d_in[9];
    float* out = (float*)d_out;

    __half *h, *q, *k, *v, *att, *h2, *ff, *wqkv, *wo, *w1, *w2;
    float *x1;
    cudaGetSymbolAddress((void**)&h,    g_h);
    cudaGetSymbolAddress((void**)&q,    g_q);
    cudaGetSymbolAddress((void**)&k,    g_k);
    cudaGetSymbolAddress((void**)&v,    g_v);
    cudaGetSymbolAddress((void**)&att,  g_att);
    cudaGetSymbolAddress((void**)&x1,   g_x1);
    cudaGetSymbolAddress((void**)&h2,   g_h2);
    cudaGetSymbolAddress((void**)&ff,   g_ff);
    cudaGetSymbolAddress((void**)&wqkv, g_wqkv);
    cudaGetSymbolAddress((void**)&wo,   g_wo);
    cudaGetSymbolAddress((void**)&w1,   g_w1);
    cudaGetSymbolAddress((void**)&w2,   g_w2);

    cudaFuncSetAttribute(attn_h, cudaFuncAttributeMaxDynamicSharedMemorySize, SM_ATTN);
    cudaFuncSetAttribute(hgemm<0>, cudaFuncAttributeMaxDynamicSharedMemorySize, SM_GEMM);
    cudaFuncSetAttribute(hgemm<2>, cudaFuncAttributeMaxDynamicSharedMemorySize, SM_GEMM);

    w_pack<<<512, 256>>>(Wq, Wk, Wv, Wo, W1, W2, wqkv, wo, w1, w2);
    ln_half<<<BT, 128>>>(x, ln1_w, h);
    hgemm<0><<<dim3(BT / 128, NQKV / 128), 256, SM_GEMM>>>(h, wqkv, nullptr, nullptr, nullptr,
                                                           q, k, v, BT, NQKV, CC);
    attn_h<<<dim3(TT / 128, HH, BB), 128, SM_ATTN>>>(q, k, v, att);
    hgemm64<1><<<dim3(BT / 64, CC / 128), 128, SM_GEMM64>>>(att, wo, x1, x, bo,
                                                            nullptr, nullptr, nullptr, BT, CC, CC);
    ln_half<<<BT, 128>>>(x1, ln2_w, h2);
    hgemm<2><<<dim3(BT / 128, FF / 128), 256, SM_GEMM>>>(h2, w1, ff, nullptr, nullptr,
                                                         nullptr, nullptr, nullptr, BT, FF, CC);
    hgemm64<3><<<dim3(BT / 64, CC / 128), 128, SM_GEMM64>>>(ff, w2, out, x1, nullptr,
                                                            nullptr, nullptr, nullptr, BT, CC, FF);
}

// round 17
// speedup vs baseline: 1.0095x; 1.0095x over previous
#include <cuda_runtime.h>
#include <cuda_fp16.h>
#include <math.h>
#include <stdint.h>

#define BB 8
#define TT 2048
#define CC 384
#define HH 6
#define HS 64
#define BT (BB*TT)     /* 16384 */
#define FF 1536
#define NQKV 1152
/* 384^-0.5 * log2(e): softmax computed as exp2 */
#define QSCALE 0.07362223f

// ---------------- scratch ----------------
__device__ __align__(256) __half g_h [BT*CC];
__device__ __align__(256) __half g_q [BT*CC];
__device__ __align__(256) __half g_k [BT*CC];
__device__ __align__(256) __half g_v [BT*CC];
__device__ __align__(256) __half g_att[BT*CC];
__device__ __align__(256) float  g_x1[BT*CC];
__device__ __align__(256) __half g_h2[BT*CC];
__device__ __align__(256) __half g_ff[BT*FF];
__device__ __align__(256) __half g_wqkv[CC*NQKV];
__device__ __align__(256) __half g_wo[CC*CC];
__device__ __align__(256) __half g_w1[CC*FF];
__device__ __align__(256) __half g_w2[FF*CC];

// ---------------- asm helpers ----------------
__device__ __forceinline__ uint32_t smem_u32(const void* p) {
    return (uint32_t)__cvta_generic_to_shared(p);
}
__device__ __forceinline__ void cp16(uint32_t s, const void* g) {
    asm volatile("cp.async.cg.shared.global [%0],[%1],16;" :: "r"(s), "l"(g));
}
__device__ __forceinline__ void cp_commit() { asm volatile("cp.async.commit_group;"); }
template<int N> __device__ __forceinline__ void cp_wait() {
    asm volatile("cp.async.wait_group %0;" :: "n"(N));
}
__device__ __forceinline__ void ldm_x4(uint32_t& r0, uint32_t& r1, uint32_t& r2, uint32_t& r3, uint32_t a) {
    asm volatile("ldmatrix.sync.aligned.m8n8.x4.shared.b16 {%0,%1,%2,%3},[%4];"
                 : "=r"(r0), "=r"(r1), "=r"(r2), "=r"(r3) : "r"(a));
}
__device__ __forceinline__ void ldm_x4t(uint32_t& r0, uint32_t& r1, uint32_t& r2, uint32_t& r3, uint32_t a) {
    asm volatile("ldmatrix.sync.aligned.m8n8.x4.trans.shared.b16 {%0,%1,%2,%3},[%4];"
                 : "=r"(r0), "=r"(r1), "=r"(r2), "=r"(r3) : "r"(a));
}
__device__ __forceinline__ void mma16(float4& d,
                                      uint32_t a0, uint32_t a1, uint32_t a2, uint32_t a3,
                                      uint32_t b0, uint32_t b1) {
    asm("mma.sync.aligned.m16n8k16.row.col.f32.f16.f16.f32 "
        "{%0,%1,%2,%3},{%4,%5,%6,%7},{%8,%9},{%0,%1,%2,%3};"
        : "+f"(d.x), "+f"(d.y), "+f"(d.z), "+f"(d.w)
        : "r"(a0), "r"(a1), "r"(a2), "r"(a3), "r"(b0), "r"(b1));
}
__device__ __forceinline__ float tanh_fast(float x) {
    float y; asm("tanh.approx.f32 %0,%1;" : "=f"(y) : "f"(x)); return y;
}
__device__ __forceinline__ uint32_t h2u(float a, float b) {
    __half2 h = __floats2half2_rn(a, b);
    return *(uint32_t*)&h;
}
__device__ __forceinline__ uint32_t hex2u(uint32_t x) {
    uint32_t y; asm("ex2.approx.f16x2 %0,%1;" : "=r"(y) : "r"(x)); return y;
}
__device__ __forceinline__ uint32_t hadd2u(uint32_t a, uint32_t b) {
    uint32_t c; asm("add.f16x2 %0,%1,%2;" : "=r"(c) : "r"(a), "r"(b)); return c;
}

// ---------------- weight convert + QKV repack ----------------
__global__ __launch_bounds__(256) void w_pack(const float* __restrict__ Wq,
                                              const float* __restrict__ Wk,
                                              const float* __restrict__ Wv,
                                              const float* __restrict__ Wo,
                                              const float* __restrict__ W1,
                                              const float* __restrict__ W2,
                                              __half* __restrict__ wqkv,
                                              __half* __restrict__ wo,
                                              __half* __restrict__ w1,
                                              __half* __restrict__ w2) {
    int t0 = blockIdx.x * 256 + threadIdx.x;
    int stride = gridDim.x * 256;
    const int NQ4 = 3 * HH * CC * HS / 4;
    for (int i = t0; i < NQ4; i += stride) {
        int d  = (i & 15) << 2;
        int c  = (i >> 4) % CC;
        int hz = i / (16 * CC);
        int z = hz / HH, hh = hz - z * HH;
        const float* W = (z == 0) ? Wq : (z == 1) ? Wk : Wv;
        float4 v = *(const float4*)&W[((size_t)hh * CC + c) * HS + d];
        __half* dst = &wqkv[(size_t)c * NQKV + z * CC + hh * HS + d];
        *(__half2*)dst       = __floats2half2_rn(v.x, v.y);
        *(__half2*)(dst + 2) = __floats2half2_rn(v.z, v.w);
    }
    for (int i = t0; i < CC * CC / 4; i += stride) {
        float4 v = *(const float4*)&Wo[i * 4];
        *(__half2*)&wo[i * 4]     = __floats2half2_rn(v.x, v.y);
        *(__half2*)&wo[i * 4 + 2] = __floats2half2_rn(v.z, v.w);
    }
    for (int i = t0; i < CC * FF / 4; i += stride) {
        float4 v = *(const float4*)&W1[i * 4];
        *(__half2*)&w1[i * 4]     = __floats2half2_rn(v.x, v.y);
        *(__half2*)&w1[i * 4 + 2] = __floats2half2_rn(v.z, v.w);
    }
    for (int i = t0; i < FF * CC / 4; i += stride) {
        float4 v = *(const float4*)&W2[i * 4];
        *(__half2*)&w2[i * 4]     = __floats2half2_rn(v.x, v.y);
        *(__half2*)&w2[i * 4 + 2] = __floats2half2_rn(v.z, v.w);
    }
}

// ---------------- LayerNorm -> half ----------------
__global__ __launch_bounds__(128) void ln_half(const float* __restrict__ x,
                                               const float* __restrict__ w,
                                               __half* __restrict__ out) {
    int row = blockIdx.x;
    const float* xr = x + (size_t)row * CC;
    int tid = threadIdx.x;
    float v0 = xr[tid], v1 = xr[tid + 128], v2 = xr[tid + 256];
    float s = v0 + v1 + v2;
    __shared__ float red[4], red2[4];
    #pragma unroll
    for (int o = 16; o > 0; o >>= 1) s += __shfl_xor_sync(0xffffffffu, s, o);
    if ((tid & 31) == 0) red[tid >> 5] = s;
    __syncthreads();
    float mean = (red[0] + red[1] + red[2] + red[3]) * (1.0f / CC);
    float d0 = v0 - mean, d1 = v1 - mean, d2 = v2 - mean;
    float q = d0*d0 + d1*d1 + d2*d2;
    #pragma unroll
    for (int o = 16; o > 0; o >>= 1) q += __shfl_xor_sync(0xffffffffu, q, o);
    if ((tid & 31) == 0) red2[tid >> 5] = q;
    __syncthreads();
    float var = (red2[0] + red2[1] + red2[2] + red2[3]) * (1.0f / CC);
    float rstd = rsqrtf(var + 1e-5f);
    __half* orow = out + (size_t)row * CC;
    orow[tid]       = __float2half(d0 * rstd * w[tid]);
    orow[tid + 128] = __float2half(d1 * rstd * w[tid + 128]);
    orow[tid + 256] = __float2half(d2 * rstd * w[tid + 256]);
}

#define AST 40     /* BK=32 A row stride */
#define A64 72     /* BK=64 A row stride (144B: conflict-free) */
#define BST 136

// ---------------- epilogue (shared) ----------------
template<int MODE>
__device__ __forceinline__ void epi_store(int r, int col, float o0, float o1, int N,
                                          void* Cout, const float* res, const float* bias,
                                          __half* qo, __half* ko, __half* vo) {
    const float cg = 0.7978845608028654f;
    if (MODE == 0) {
        int z = col / CC; int rem = col - z * CC;
        int hh = rem >> 6, d = rem & 63;
        __half* Oz = (z == 0) ? qo : (z == 1) ? ko : vo;
        float sc = (z == 0) ? QSCALE : 1.0f;
        int bb = r >> 11, t = r & (TT - 1);
        *(__half2*)&Oz[((size_t)(bb * HH + hh) * TT + t) * HS + d] =
            __floats2half2_rn(o0 * sc, o1 * sc);
    } else if (MODE == 1) {
        float2 rr = *(const float2*)&res[(size_t)r * N + col];
        float2 bb = *(const float2*)&bias[col];
        *(float2*)((float*)Cout + (size_t)r * N + col) =
            make_float2(o0 + rr.x + bb.x, o1 + rr.y + bb.y);
    } else if (MODE == 2) {
        o0 = 0.5f * o0 * (1.0f + tanh_fast(cg * (o0 + 0.044715f * o0 * o0 * o0)));
        o1 = 0.5f * o1 * (1.0f + tanh_fast(cg * (o1 + 0.044715f * o1 * o1 * o1)));
        *(__half2*)((__half*)Cout + (size_t)r * N + col) = __floats2half2_rn(o0, o1);
    } else {
        float2 rr = *(const float2*)&res[(size_t)r * N + col];
        *(float2*)((float*)Cout + (size_t)r * N + col) =
            make_float2(o0 + rr.x, o1 + rr.y);
    }
}

// ---------------- fp16 GEMM A: 128x128x64 tiles, 256 thr, 3-stage, 2 CTAs/SM ----------------
#define SM_GEMM ((3*128*A64 + 3*64*BST) * 2)   /* 107520 B */
template<int MODE>
__global__ __launch_bounds__(256, 2) void hgemm(const __half* __restrict__ A,
                                                const __half* __restrict__ B,
                                                void* __restrict__ Cout,
                                                const float* __restrict__ res,
                                                const float* __restrict__ bias,
                                                __half* __restrict__ qo,
                                                __half* __restrict__ ko,
                                                __half* __restrict__ vo,
                                                int M, int N, int K) {
    extern __shared__ __half smg[];
    __half* Asm = smg;                    // [3][128*A64]
    __half* Bsm = smg + 3 * 128 * A64;    // [3][64*BST]
    int bm = blockIdx.x * 128, bn = blockIdx.y * 128;
    int tid = threadIdx.x;
    int wid = tid >> 5, lane = tid & 31, g = lane >> 2, tg = lane & 3;
    int wm = wid >> 2, wn = wid & 3;
    int l4 = lane & 15, lh = lane >> 4;
    float4 acc[4][4];
    #pragma unroll
    for (int i = 0; i < 4; i++)
        #pragma unroll
        for (int j = 0; j < 4; j++) acc[i][j] = make_float4(0.f, 0.f, 0.f, 0.f);

    int KT = K >> 6;   /* BK = 64 */
    auto load_tile = [&](int kt, int st) {
        __half* As = Asm + st * 128 * A64;
        __half* Bs = Bsm + st * 64 * BST;
        const __half* Ag = A + (size_t)bm * K + kt * 64;
        const __half* Bg = B + (size_t)(kt * 64) * N + bn;
        #pragma unroll
        for (int i = 0; i < 4; i++) {       // A: 128r x 8 chunks = 1024
            int e = tid + i * 256;
            int r = e >> 3, c = e & 7;
            cp16(smem_u32(&As[r * A64 + c * 8]), Ag + (size_t)r * K + c * 8);
        }
        #pragma unroll
        for (int i = 0; i < 4; i++) {       // B: 64r x 16 chunks = 1024
            int e = tid + i * 256;
            int r = e >> 4, c = e & 15;
            cp16(smem_u32(&Bs[r * BST + c * 8]), Bg + (size_t)r * N + c * 8);
        }
        cp_commit();
    };
    load_tile(0, 0);
    if (KT > 1) load_tile(1, 1);

    for (int kt = 0; kt < KT; kt++) {
        int st = kt % 3;
        if (kt + 1 < KT) cp_wait<1>(); else cp_wait<0>();
        __syncthreads();
        __half* As = Asm + st * 128 * A64;
        __half* Bs = Bsm + st * 64 * BST;
        if (kt + 2 < KT) load_tile(kt + 2, (kt + 2) % 3);
        #pragma unroll
        for (int ks = 0; ks < 4; ks++) {
            uint32_t aF[4][4];
            #pragma unroll
            for (int mt = 0; mt < 4; mt++) {
                int row = wm * 64 + mt * 16 + l4;
                ldm_x4(aF[mt][0], aF[mt][1], aF[mt][2], aF[mt][3],
                       smem_u32(&As[row * A64 + ks * 16 + lh * 8]));
            }
            #pragma unroll
            for (int ntp = 0; ntp < 2; ntp++) {
                uint32_t b00, b01, b10, b11;
                int n0 = wn * 32 + ntp * 16;
                ldm_x4t(b00, b01, b10, b11,
                        smem_u32(&Bs[(ks * 16 + l4) * BST + n0 + lh * 8]));
                #pragma unroll
                for (int mt = 0; mt < 4; mt++) {
                    mma16(acc[mt][ntp * 2],     aF[mt][0], aF[mt][1], aF[mt][2], aF[mt][3], b00, b01);
                    mma16(acc[mt][ntp * 2 + 1], aF[mt][0], aF[mt][1], aF[mt][2], aF[mt][3], b10, b11);
                }
            }
        }
    }
    #pragma unroll
    for (int mt = 0; mt < 4; mt++)
        #pragma unroll
        for (int nt = 0; nt < 4; nt++) {
            int r0 = bm + wm * 64 + mt * 16 + g;
            int col = bn + wn * 32 + nt * 8 + tg * 2;
            float vv[4] = {acc[mt][nt].x, acc[mt][nt].y, acc[mt][nt].z, acc[mt][nt].w};
            #pragma unroll
            for (int hf = 0; hf < 2; hf++)
                epi_store<MODE>(r0 + hf * 8, col, vv[hf * 2], vv[hf * 2 + 1],
                                N, Cout, res, bias, qo, ko, vo);
        }
}

// ---------------- fp16 GEMM B: 64x128x32, 128 thr, 4 CTAs/SM (small grids) ----------------
#define SM_GEMM64 ((3*64*AST + 3*32*BST) * 2)
template<int MODE>
__global__ __launch_bounds__(128, 4) void hgemm64(const __half* __restrict__ A,
                                                  const __half* __restrict__ B,
                                                  void* __restrict__ Cout,
                                                  const float* __restrict__ res,
                                                  const float* __restrict__ bias,
                                                  __half* __restrict__ qo,
                                                  __half* __restrict__ ko,
                                                  __half* __restrict__ vo,
                                                  int M, int N, int K) {
    extern __shared__ __half smg[];
    __half* Asm = smg;
    __half* Bsm = smg + 3 * 64 * AST;
    int bm = blockIdx.x * 64, bn = blockIdx.y * 128;
    int tid = threadIdx.x;
    int wid = tid >> 5, lane = tid & 31, g = lane >> 2, tg = lane & 3;
    int wm = wid >> 1, wn = wid & 1;
    int l4 = lane & 15, lh = lane >> 4;
    float4 acc[2][8];
    #pragma unroll
    for (int i = 0; i < 2; i++)
        #pragma unroll
        for (int j = 0; j < 8; j++) acc[i][j] = make_float4(0.f, 0.f, 0.f, 0.f);

    int KT = K >> 5;
    int ar0 = tid >> 2, ac0 = tid & 3;
    int ar1 = (tid + 128) >> 2;
    int brr = tid >> 4, bcc = tid & 15;
    auto load_tile = [&](int kt, int st) {
        __half* As = Asm + st * 64 * AST;
        __half* Bs = Bsm + st * 32 * BST;
        const __half* Ag = A + (size_t)bm * K + kt * 32;
        const __half* Bg = B + (size_t)(kt * 32) * N + bn;
        cp16(smem_u32(&As[ar0 * AST + ac0 * 8]), Ag + (size_t)ar0 * K + ac0 * 8);
        cp16(smem_u32(&As[ar1 * AST + ac0 * 8]), Ag + (size_t)ar1 * K + ac0 * 8);
        #pragma unroll
        for (int j = 0; j < 4; j++)
            cp16(smem_u32(&Bs[(brr + j * 8) * BST + bcc * 8]),
                 Bg + (size_t)(brr + j * 8) * N + bcc * 8);
        cp_commit();
    };
    load_tile(0, 0);
    if (KT > 1) load_tile(1, 1);

    for (int kt = 0; kt < KT; kt++) {
        int st = kt % 3;
        if (kt + 1 < KT) cp_wait<1>(); else cp_wait<0>();
        __syncthreads();
        __half* As = Asm + st * 64 * AST;
        __half* Bs = Bsm + st * 32 * BST;
        if (kt + 2 < KT) load_tile(kt + 2, (kt + 2) % 3);
        #pragma unroll
        for (int ks = 0; ks < 2; ks++) {
            uint32_t aF[2][4];
            #pragma unroll
            for (int mt = 0; mt < 2; mt++) {
                int row = wm * 32 + mt * 16 + l4;
                ldm_x4(aF[mt][0], aF[mt][1], aF[mt][2], aF[mt][3],
                       smem_u32(&As[row * AST + ks * 16 + lh * 8]));
            }
            #pragma unroll
            for (int ntp = 0; ntp < 4; ntp++) {
                uint32_t b00, b01, b10, b11;
                int n0 = wn * 64 + ntp * 16;
                ldm_x4t(b00, b01, b10, b11,
                        smem_u32(&Bs[(ks * 16 + l4) * BST + n0 + lh * 8]));
                #pragma unroll
                for (int mt = 0; mt < 2; mt++) {
                    mma16(acc[mt][ntp * 2],     aF[mt][0], aF[mt][1], aF[mt][2], aF[mt][3], b00, b01);
                    mma16(acc[mt][ntp * 2 + 1], aF[mt][0], aF[mt][1], aF[mt][2], aF[mt][3], b10, b11);
                }
            }
        }
    }
    #pragma unroll
    for (int mt = 0; mt < 2; mt++)
        #pragma unroll
        for (int nt = 0; nt < 8; nt++) {
            int r0 = bm + wm * 32 + mt * 16 + g;
            int col = bn + wn * 64 + nt * 8 + tg * 2;
            float vv[4] = {acc[mt][nt].x, acc[mt][nt].y, acc[mt][nt].z, acc[mt][nt].w};
            #pragma unroll
            for (int hf = 0; hf < 2; hf++)
                epi_store<MODE>(r0 + hf * 8, col, vv[hf * 2], vv[hf * 2 + 1],
                                N, Cout, res, bias, qo, ko, vo);
        }
}

// ---------------- fp16 flash attention (R13 best variant) ----------------
#define SM_ATTN ((128*64 + 2*64*64 + 2*64*64) * 2)   /* 48 KB */
__global__ __launch_bounds__(256, 2) void attn_h(const __half* __restrict__ Q,
                                                 const __half* __restrict__ K,
                                                 const __half* __restrict__ V,
                                                 __half* __restrict__ Og) {
    extern __shared__ __half sm[];
    __half* Qs = sm;
    __half* Ks = Qs + 128 * 64;
    __half* Vs = Ks + 2 * 64 * 64;

    int q0 = blockIdx.x * 128;
    int h = blockIdx.y, b = blockIdx.z;
    size_t base = (size_t)(b * HH + h) * TT * HS;
    int tid = threadIdx.x;
    int wid = tid >> 5, lane = tid & 31, g = lane >> 2, tg = lane & 3;
    int l4 = lane & 15, lh = lane >> 4;

    const __half* Qp = Q + base + (size_t)q0 * HS;
    #pragma unroll
    for (int i = 0; i < 4; i++) {
        int idx = tid + i * 256;
        int r = idx >> 3, c = idx & 7;
        cp16(smem_u32(&Qs[r * 64 + ((c ^ (r & 7)) << 3)]), Qp + (size_t)r * HS + c * 8);
    }
    auto load_kv = [&](int it, int buf) {
        const __half* Kp = K + base + (size_t)(it * 64) * HS;
        const __half* Vp = V + base + (size_t)(it * 64) * HS;
        #pragma unroll
        for (int i = 0; i < 2; i++) {
            int idx = tid + i * 256;
            int r = idx >> 3, c = idx & 7;
            int sp = buf * 4096 + r * 64 + ((c ^ (r & 7)) << 3);
            cp16(smem_u32(&Ks[sp]), Kp + (size_t)r * HS + c * 8);
            cp16(smem_u32(&Vs[sp]), Vp + (size_t)r * HS + c * 8);
        }
    };
    load_kv(0, 0);
    cp_commit();
    load_kv(1, 1);
    cp_commit();
    cp_wait<1>();
    __syncthreads();

    uint32_t qF[4][4];
    int qrow = (wid << 4) + l4;
    #pragma unroll
    for (int dk = 0; dk < 4; dk++) {
        int ch = dk * 2 + lh;
        ldm_x4(qF[dk][0], qF[dk][1], qF[dk][2], qF[dk][3],
               smem_u32(&Qs[qrow * 64 + ((ch ^ (qrow & 7)) << 3)]));
    }

    int krow_base = (lane & 7) + ((lane & 16) >> 1);
    int kch_half = (lane >> 3) & 1;
    uint32_t Kb0 = smem_u32(Ks), Vb0 = smem_u32(Vs);
    uint32_t koff[4], voff[4];
    #pragma unroll
    for (int dk = 0; dk < 4; dk++) {
        int ch = dk * 2 + kch_half;
        koff[dk] = (uint32_t)(krow_base * 128 + (((ch ^ (krow_base & 7)) << 4)));
    }
    #pragma unroll
    for (int np = 0; np < 4; np++) {
        int ch = np * 2 + lh;
        voff[np] = (uint32_t)(l4 * 128 + (((ch ^ (l4 & 7)) << 4)));
    }

    float4 Oacc[8];
    #pragma unroll
    for (int j = 0; j < 8; j++) Oacc[j] = make_float4(0.f, 0.f, 0.f, 0.f);
    float ls0 = 0.f, ls1 = 0.f;

    const int NT = TT / 64;
    for (int it = 0; it < NT; it++) {
        int buf = it & 1;
        uint32_t kb = Kb0 + buf * 8192;
        uint32_t vb = Vb0 + buf * 8192;

        float4 S0[4], S1[4];
        #pragma unroll
        for (int n = 0; n < 4; n++) {
            S0[n] = make_float4(0.f, 0.f, 0.f, 0.f);
            S1[n] = make_float4(0.f, 0.f, 0.f, 0.f);
        }
        #pragma unroll
        for (int dk = 0; dk < 4; dk++) {
            #pragma unroll
            for (int ntp = 0; ntp < 4; ntp++) {
                uint32_t k0, k1, k2, k3;
                ldm_x4(k0, k1, k2, k3, kb + ntp * 2048 + koff[dk]);
                mma16(S0[ntp], qF[dk][0], qF[dk][1], qF[dk][2], qF[dk][3], k0, k1);
                mma16(S1[ntp], qF[dk][0], qF[dk][1], qF[dk][2], qF[dk][3], k2, k3);
            }
        }
        uint32_t P0[4], P1[4], P2[4], P3[4];
        uint32_t hacc0 = 0u, hacc1 = 0u;
        #pragma unroll
        for (int ntp = 0; ntp < 4; ntp++) {
            uint32_t p0 = hex2u(h2u(S0[ntp].x, S0[ntp].y));
            uint32_t p1 = hex2u(h2u(S0[ntp].z, S0[ntp].w));
            uint32_t p2 = hex2u(h2u(S1[ntp].x, S1[ntp].y));
            uint32_t p3 = hex2u(h2u(S1[ntp].z, S1[ntp].w));
            hacc0 = hadd2u(hacc0, hadd2u(p0, p2));
            hacc1 = hadd2u(hacc1, hadd2u(p1, p3));
            P0[ntp] = p0; P1[ntp] = p1; P2[ntp] = p2; P3[ntp] = p3;
        }
        #pragma unroll
        for (int ntp = 0; ntp < 4; ntp++) {
            uint32_t vbase = vb + ntp * 2048;
            #pragma unroll
            for (int np = 0; np < 4; np++) {
                uint32_t v0, v1, v2, v3;
                ldm_x4t(v0, v1, v2, v3, vbase + voff[np]);
                mma16(Oacc[np * 2],     P0[ntp], P1[ntp], P2[ntp], P3[ntp], v0, v1);
                mma16(Oacc[np * 2 + 1], P0[ntp], P1[ntp], P2[ntp], P3[ntp], v2, v3);
            }
        }
        {
            float2 f0 = __half22float2(*(__half2*)&hacc0);
            float2 f1 = __half22float2(*(__half2*)&hacc1);
            ls0 += f0.x + f0.y;
            ls1 += f1.x + f1.y;
        }
        __syncthreads();
        if (it + 2 < NT) { load_kv(it + 2, buf); cp_commit(); }
        if (it + 1 < NT) {
            if (it + 2 < NT) cp_wait<1>(); else cp_wait<0>();
            __syncthreads();
        }
    }
    ls0 += __shfl_xor_sync(0xffffffffu, ls0, 1);
    ls0 += __shfl_xor_sync(0xffffffffu, ls0, 2);
    ls1 += __shfl_xor_sync(0xffffffffu, ls1, 1);
    ls1 += __shfl_xor_sync(0xffffffffu, ls1, 2);
    float i0 = 1.0f / ls0, i1 = 1.0f / ls1;
    int r0 = q0 + (wid << 4) + g;
    #pragma unroll
    for (int nt = 0; nt < 8; nt++) {
        int col = h * HS + nt * 8 + tg * 2;
        *(__half2*)&Og[(size_t)(b * TT + r0) * CC + col] =
            __floats2half2_rn(Oacc[nt].x * i0, Oacc[nt].y * i0);
        *(__half2*)&Og[(size_t)(b * TT + r0 + 8) * CC + col] =
            __floats2half2_rn(Oacc[nt].z * i1, Oacc[nt].w * i1);
    }
}

// ---------------- launch ----------------
extern "C" void kernel_launch(void* const* d_in, const int* in_sizes, int n_in,
                              void* d_out, int out_size) {
    (void)in_sizes; (void)n_in; (void)out_size;
    const float* x     = (const float*)d_in[0];
    const float* ln1_w = (const float*)d_in[1];
    const float* ln2_w = (const float*)d_in[2];
    const float* Wq    = (const float*)d_in[3];
    const float* Wk    = (const float*)d_in[4];
    const float* Wv    = (const float*)d_in[5];
    const float* Wo    = (const float*)d_in[6];
    const float* bo    = (const float*)d_in[7];
    const float* W1    = (const float*)d_in[8];
    const float* W2    = (const float*)d_in[9];
    float* out = (float*)d_out;

    __half *h, *q, *k, *v, *att, *h2, *ff, *wqkv, *wo, *w1, *w2;
    float *x1;
    cudaGetSymbolAddress((void**)&h,    g_h);
    cudaGetSymbolAddress((void**)&q,    g_q);
    cudaGetSymbolAddress((void**)&k,    g_k);
    cudaGetSymbolAddress((void**)&v,    g_v);
    cudaGetSymbolAddress((void**)&att,  g_att);
    cudaGetSymbolAddress((void**)&x1,   g_x1);
    cudaGetSymbolAddress((void**)&h2,   g_h2);
    cudaGetSymbolAddress((void**)&ff,   g_ff);
    cudaGetSymbolAddress((void**)&wqkv, g_wqkv);
    cudaGetSymbolAddress((void**)&wo,   g_wo);
    cudaGetSymbolAddress((void**)&w1,   g_w1);
    cudaGetSymbolAddress((void**)&w2,   g_w2);

    cudaFuncSetAttribute(attn_h, cudaFuncAttributeMaxDynamicSharedMemorySize, SM_ATTN);
    cudaFuncSetAttribute(hgemm<0>, cudaFuncAttributeMaxDynamicSharedMemorySize, SM_GEMM);
    cudaFuncSetAttribute(hgemm<2>, cudaFuncAttributeMaxDynamicSharedMemorySize, SM_GEMM);

    w_pack<<<512, 256>>>(Wq, Wk, Wv, Wo, W1, W2, wqkv, wo, w1, w2);
    ln_half<<<BT, 128>>>(x, ln1_w, h);
    hgemm<0><<<dim3(BT / 128, NQKV / 128), 256, SM_GEMM>>>(h, wqkv, nullptr, nullptr, nullptr,
                                                           q, k, v, BT, NQKV, CC);
    attn_h<<<dim3(TT / 128, HH, BB), 256, SM_ATTN>>>(q, k, v, att);
    hgemm64<1><<<dim3(BT / 64, CC / 128), 128, SM_GEMM64>>>(att, wo, x1, x, bo,
                                                            nullptr, nullptr, nullptr, BT, CC, CC);
    ln_half<<<BT, 128>>>(x1, ln2_w, h2);
    hgemm<2><<<dim3(BT / 128, FF / 128), 256, SM_GEMM>>>(h2, w1, ff, nullptr, nullptr,
                                                         nullptr, nullptr, nullptr, BT, FF, CC);
    hgemm64<3><<<dim3(BT / 64, CC / 128), 128, SM_GEMM64>>>(ff, w2, out, x1, nullptr,
                                                            nullptr, nullptr, nullptr, BT, CC, FF);
}